// round 15
// baseline (speedup 1.0000x reference)
#include <cuda_runtime.h>
#include <cuda_fp16.h>
#include <math.h>
#include <stdint.h>

// ---------------- Problem constants ----------------
#define BATCH   8
#define DIM     512
#define LEN     2048
#define GIN     256
#define NFFT    1024
#define HOP     256
#define WIN     1024
#define OUT_DIM 1026
#define PADP    384
#define KS      5
#define OUTLEN  524288
#define M1      1536
#define MOPAD   1152

// irfft symmetric split: C part M=640 (513 valid) x K=544 (513 valid); S part 512 x 512
#define MC      640
#define KC      544
#define MS      512
#define KSR     512
#define FRN     1152   // frames row: [C 0..639 | S 640..1151]

// ---------------- Device scratch (static, no allocation) ----------------
__device__ __align__(256) __half g_h0h [BATCH * DIM * LEN];
__device__ __align__(256) __half g_h0l [BATCH * DIM * LEN];
__device__ __align__(256) __half g_h1h [BATCH * M1 * LEN];
__device__ __align__(256) __half g_h1l [BATCH * M1 * LEN];
__device__ __align__(256) __half g_h2h [BATCH * DIM * LEN];
__device__ __align__(256) __half g_h2l [BATCH * DIM * LEN];
__device__ __align__(256) float  g_h3  [BATCH * MOPAD * LEN];
__device__ __align__(256) __half g_sriCh[BATCH * KC  * LEN];
__device__ __align__(256) __half g_sriCl[BATCH * KC  * LEN];
__device__ __align__(256) __half g_sriSh[BATCH * KSR * LEN];
__device__ __align__(256) __half g_sriSl[BATCH * KSR * LEN];
__device__ __align__(256) float  g_frames[BATCH * LEN * FRN];  // [b][t][C|S]
__device__ __align__(256) __half g_w1h[BATCH * M1 * DIM];
__device__ __align__(256) __half g_w1l[BATCH * M1 * DIM];
__device__ __align__(256) __half g_w2h[BATCH * DIM * M1];
__device__ __align__(256) __half g_w2l[BATCH * DIM * M1];
__device__ __align__(256) __half g_woh[BATCH * MOPAD * DIM];
__device__ __align__(256) __half g_wol[BATCH * MOPAD * DIM];
__device__ __align__(256) __half g_Fch[MC * KC];
__device__ __align__(256) __half g_Fcl[MC * KC];
__device__ __align__(256) __half g_Fsh[MS * KSR];
__device__ __align__(256) __half g_Fsl[MS * KSR];
__device__ float g_vin1 [BATCH * DIM * 12];
__device__ float g_vout1[BATCH * 12 * M1];
__device__ float g_vin2 [BATCH * M1 * 12];
__device__ float g_vout2[BATCH * 12 * DIM];
__device__ float g_vino [BATCH * DIM * 16];
__device__ float g_vouto[BATCH * 16 * OUT_DIM];

// ---------------- PTX helpers (base ISA only) ----------------
__device__ __forceinline__ uint32_t smem_u32(const void* p) {
    uint32_t a;
    asm("{ .reg .u64 t; cvta.to.shared.u64 t, %1; cvt.u32.u64 %0, t; }" : "=r"(a) : "l"(p));
    return a;
}

__device__ __forceinline__ void cp16(uint32_t dst, const void* src) {
    asm volatile("cp.async.cg.shared.global [%0], [%1], 16;" :: "r"(dst), "l"(src));
}
#define CP_COMMIT() asm volatile("cp.async.commit_group;" ::: "memory")
template<int N> __device__ __forceinline__ void cp_wait() {
    asm volatile("cp.async.wait_group %0;" :: "n"(N) : "memory");
}

__device__ __forceinline__ void ldsm_x4(uint32_t* r, uint32_t addr) {
    asm volatile("ldmatrix.sync.aligned.m8n8.x4.shared.b16 {%0,%1,%2,%3}, [%4];"
                 : "=r"(r[0]), "=r"(r[1]), "=r"(r[2]), "=r"(r[3]) : "r"(addr));
}
__device__ __forceinline__ void ldsm_x4t(uint32_t* r, uint32_t addr) {
    asm volatile("ldmatrix.sync.aligned.m8n8.x4.trans.shared.b16 {%0,%1,%2,%3}, [%4];"
                 : "=r"(r[0]), "=r"(r[1]), "=r"(r[2]), "=r"(r[3]) : "r"(addr));
}

__device__ __forceinline__ void mma16816(float* c, const uint32_t* a, const uint32_t* b) {
    asm volatile("mma.sync.aligned.m16n8k16.row.col.f32.f16.f16.f32 "
                 "{%0,%1,%2,%3}, {%4,%5,%6,%7}, {%8,%9}, {%0,%1,%2,%3};"
                 : "+f"(c[0]), "+f"(c[1]), "+f"(c[2]), "+f"(c[3])
                 : "r"(a[0]), "r"(a[1]), "r"(a[2]), "r"(a[3]), "r"(b[0]), "r"(b[1]));
}

__device__ __forceinline__ float gelu_f(float v) {
    return 0.5f * v * (1.0f + erff(v * 0.70710678118654752f));
}

// ---------------- HMMA GEMM (3-stage pipeline, single-barrier mainloop) ----------------
// C[b][m][n] = sum_k A[b?][m][k] * B[b][k][n], hi/lo split operands (hh+hl+lh).
// BM=128 (blockIdx.y), BN=128 (blockIdx.x over LEN/128), batch=blockIdx.z.
// mode 0: +bias, gelu, write half hi/lo.  mode 1: +bias, fp32 [m][n].
// mode 2: fp32 TRANSPOSED frames rows; Mvalid = frame row stride (FRN), no bias.
#define BK 32
#define ASTR 80
#define BSTR 272
#define OFF_AH 0
#define OFF_AL 10240
#define OFF_BH 20480
#define OFF_BL 29184
#define SSTR   37888
#define NSTAGE 3
#define SMEM_TOT (NSTAGE * SSTR)
#define STG_STRIDE 132

__global__ __launch_bounds__(256, 2)
void hmma_gemm(const __half* __restrict__ Ah, const __half* __restrict__ Al,
               const __half* __restrict__ Bh, const __half* __restrict__ Bl,
               const float* __restrict__ bias,
               void* __restrict__ Ch, void* __restrict__ Cl,
               int M, int K, int Mvalid, int mode, int aBatched)
{
    extern __shared__ char smem[];
    uint32_t sb = smem_u32(smem);
    int tid = threadIdx.x, lane = tid & 31, wid = tid >> 5;
    int wm = wid & 3, wn = wid >> 2;
    int bz = blockIdx.z;
    int M0 = blockIdx.y * 128, N0 = blockIdx.x * 128;
    const int N = LEN;

    const __half* Abh = Ah + (aBatched ? (long)bz * M * K : 0);
    const __half* Abl = Al + (aBatched ? (long)bz * M * K : 0);
    const __half* Bbh = Bh + (long)bz * (long)K * N;
    const __half* Bbl = Bl + (long)bz * (long)K * N;

    int a_row = tid >> 2, a_col = tid & 3;
    int b_row = tid >> 4, b_col = tid & 15;

    float acc[2][8][4];
    #pragma unroll
    for (int i = 0; i < 2; i++)
        #pragma unroll
        for (int j = 0; j < 8; j++)
            #pragma unroll
            for (int q = 0; q < 4; q++) acc[i][j][q] = 0.f;

    int nIter = K / BK;

    auto load_stage = [&](int kc, int s) {
        uint32_t base = sb + s * SSTR;
        long ga0 = (long)(M0 + a_row) * K + kc * BK + a_col * 8;
        long ga1 = (long)(M0 + a_row + 64) * K + kc * BK + a_col * 8;
        cp16(base + OFF_AH + a_row * ASTR + a_col * 16, Abh + ga0);
        cp16(base + OFF_AH + (a_row + 64) * ASTR + a_col * 16, Abh + ga1);
        cp16(base + OFF_AL + a_row * ASTR + a_col * 16, Abl + ga0);
        cp16(base + OFF_AL + (a_row + 64) * ASTR + a_col * 16, Abl + ga1);
        long gb0 = (long)(kc * BK + b_row) * N + N0 + b_col * 8;
        long gb1 = (long)(kc * BK + b_row + 16) * N + N0 + b_col * 8;
        cp16(base + OFF_BH + b_row * BSTR + b_col * 16, Bbh + gb0);
        cp16(base + OFF_BH + (b_row + 16) * BSTR + b_col * 16, Bbh + gb1);
        cp16(base + OFF_BL + b_row * BSTR + b_col * 16, Bbl + gb0);
        cp16(base + OFF_BL + (b_row + 16) * BSTR + b_col * 16, Bbl + gb1);
        CP_COMMIT();
    };

    load_stage(0, 0);
    load_stage(1, 1);
    int s_cur = 0, s_load = 2;
    for (int it = 0; it < nIter; it++) {
        cp_wait<1>();
        __syncthreads();
        if (it + 2 < nIter) {
            load_stage(it + 2, s_load);
        }
        uint32_t base = sb + s_cur * SSTR;
        s_cur = (s_cur + 1 == NSTAGE) ? 0 : s_cur + 1;
        s_load = (s_load + 1 == NSTAGE) ? 0 : s_load + 1;

        #pragma unroll
        for (int ks = 0; ks < 2; ks++) {
            uint32_t ah[2][4], al[2][4];
            #pragma unroll
            for (int mt = 0; mt < 2; mt++) {
                uint32_t addr = base + OFF_AH
                    + (uint32_t)(wm * 32 + mt * 16 + (lane & 15)) * ASTR
                    + (uint32_t)(ks * 32 + (lane >> 4) * 16);
                ldsm_x4(ah[mt], addr);
                ldsm_x4(al[mt], addr + (OFF_AL - OFF_AH));
            }
            #pragma unroll
            for (int half = 0; half < 2; half++) {
                uint32_t bh[4][2], bl[4][2];
                #pragma unroll
                for (int j = 0; j < 2; j++) {
                    uint32_t rh[4], rl[4];
                    uint32_t addr = base + OFF_BH
                        + (uint32_t)(ks * 16 + (lane & 15)) * BSTR
                        + (uint32_t)(wn * 128 + half * 64 + j * 32 + (lane >> 4) * 16);
                    ldsm_x4t(rh, addr);
                    ldsm_x4t(rl, addr + (OFF_BL - OFF_BH));
                    bh[j*2][0] = rh[0]; bh[j*2][1] = rh[1];
                    bh[j*2+1][0] = rh[2]; bh[j*2+1][1] = rh[3];
                    bl[j*2][0] = rl[0]; bl[j*2][1] = rl[1];
                    bl[j*2+1][0] = rl[2]; bl[j*2+1][1] = rl[3];
                }
                #pragma unroll
                for (int mt = 0; mt < 2; mt++)
                    #pragma unroll
                    for (int j = 0; j < 4; j++) {
                        int nt = half * 4 + j;
                        mma16816(acc[mt][nt], ah[mt], bh[j]);
                        mma16816(acc[mt][nt], ah[mt], bl[j]);
                        mma16816(acc[mt][nt], al[mt], bh[j]);
                    }
            }
        }
        // no trailing barrier: with 3 stages, slot (it+2)%3 written next iter was
        // last read in iter it-1, ordered by every warp's top-of-loop barrier.
    }

    // ---- epilogue ----
    if (mode == 2) {
        __syncthreads();   // smem reuse: all warps done with mainloop stages
        int frn = Mvalid;  // frames row stride
        float* stg = (float*)smem;
        #pragma unroll
        for (int mt = 0; mt < 2; mt++)
            #pragma unroll
            for (int h = 0; h < 2; h++) {
                int m_loc = wm * 32 + mt * 16 + h * 8 + (lane >> 2);
                #pragma unroll
                for (int nt = 0; nt < 8; nt++) {
                    int n_loc = wn * 64 + nt * 8 + (lane & 3) * 2;
                    stg[(long)n_loc * STG_STRIDE + m_loc] = acc[mt][nt][h * 2 + 0];
                    stg[(long)(n_loc + 1) * STG_STRIDE + m_loc] = acc[mt][nt][h * 2 + 1];
                }
            }
        __syncthreads();
        int tt = tid >> 1, hf = tid & 1;
        float* dst = (float*)Ch + ((long)bz * LEN + N0 + tt) * frn + M0 + hf * 64;
        const float* src = stg + (long)tt * STG_STRIDE + hf * 64;
        #pragma unroll
        for (int j = 0; j < 64; j += 4)
            *reinterpret_cast<float4*>(dst + j) = *reinterpret_cast<const float4*>(src + j);
        return;
    }

    int rbase = M0 + wm * 32 + (lane >> 2);
    int cbase = N0 + wn * 64 + (lane & 3) * 2;
    #pragma unroll
    for (int mt = 0; mt < 2; mt++) {
        #pragma unroll
        for (int h = 0; h < 2; h++) {
            int row = rbase + mt * 16 + h * 8;
            float bv = (row < Mvalid) ? bias[row] : 0.f;
            #pragma unroll
            for (int nt = 0; nt < 8; nt++) {
                float v0 = acc[mt][nt][h * 2 + 0] + bv;
                float v1 = acc[mt][nt][h * 2 + 1] + bv;
                long off = (long)bz * M * N + (long)row * N + cbase + nt * 8;
                if (mode == 0) {
                    float gq0 = gelu_f(v0), gq1 = gelu_f(v1);
                    __half h0 = __float2half(gq0), h1 = __float2half(gq1);
                    __half l0 = __float2half(gq0 - __half2float(h0));
                    __half l1 = __float2half(gq1 - __half2float(h1));
                    *reinterpret_cast<__half2*>((__half*)Ch + off) = __halves2half2(h0, h1);
                    *reinterpret_cast<__half2*>((__half*)Cl + off) = __halves2half2(l0, l1);
                } else {
                    *reinterpret_cast<float2*>((float*)Ch + off) = make_float2(v0, v1);
                }
            }
        }
    }
}

// ---------------- small kernels ----------------
// fused 6-way gemv. aout outputs are written TRANSPOSED to [b][outch][r].
#define GV_R0 6144
#define GV_R1 18432
#define GV_R2 18432
#define GV_R3 6144
#define GV_R4 8192
#define GV_R5 16416
#define GV_E0 (GV_R0 * BATCH)
#define GV_E1 (GV_E0 + GV_R1 * BATCH)
#define GV_E2 (GV_E1 + GV_R2 * BATCH)
#define GV_E3 (GV_E2 + GV_R3 * BATCH)
#define GV_E4 (GV_E3 + GV_R4 * BATCH)
#define GV_E5 (GV_E4 + GV_R5 * BATCH)
#define GV_BLOCKS (GV_E5 / 8)

__global__ void gemv_all_kernel(const float* __restrict__ gvec,
                                const float* __restrict__ m0, float* __restrict__ o0,
                                const float* __restrict__ m1, float* __restrict__ o1,
                                const float* __restrict__ m2, float* __restrict__ o2,
                                const float* __restrict__ m3, float* __restrict__ o3,
                                const float* __restrict__ m4, float* __restrict__ o4,
                                const float* __restrict__ m5, float* __restrict__ o5)
{
    int w    = (blockIdx.x * blockDim.x + threadIdx.x) >> 5;
    int lane = threadIdx.x & 31;
    const float* mat; float* out; int rows, local, outch;
    if      (w < GV_E0) { mat = m0; out = o0; rows = GV_R0; local = w;         outch = 0; }
    else if (w < GV_E1) { mat = m1; out = o1; rows = GV_R1; local = w - GV_E0; outch = M1; }
    else if (w < GV_E2) { mat = m2; out = o2; rows = GV_R2; local = w - GV_E1; outch = 0; }
    else if (w < GV_E3) { mat = m3; out = o3; rows = GV_R3; local = w - GV_E2; outch = DIM; }
    else if (w < GV_E4) { mat = m4; out = o4; rows = GV_R4; local = w - GV_E3; outch = 0; }
    else if (w < GV_E5) { mat = m5; out = o5; rows = GV_R5; local = w - GV_E4; outch = OUT_DIM; }
    else return;
    int b = local / rows, o = local - b * rows;
    const float* r = mat + (long)o * GIN;
    const float* g = gvec + (long)b * GIN;
    float s = 0.f;
    #pragma unroll
    for (int i = 0; i < GIN / 32; i++) s += r[lane + 32 * i] * g[lane + 32 * i];
    #pragma unroll
    for (int off = 16; off; off >>= 1) s += __shfl_xor_sync(0xffffffffu, s, off);
    if (lane == 0) {
        int dst = o;
        if (outch) {
            int rr = o / outch, oc = o - rr * outch;
            int rfac = rows / outch;
            dst = oc * rfac + rr;
        }
        out[(long)b * rows + dst] = s;
    }
}

// vectorized weff build: grid (Mpad, BATCH), block inch/8; 8 consecutive i per thread.
// vo[r] hoisted to registers; uint4 hi/lo stores. Per-element accumulation order
// identical to the scalar version (W + sum_rr vo*vi).
__global__ void build_weff_kernel(const float* __restrict__ W, const float* __restrict__ vin,
                                  const float* __restrict__ vout,
                                  __half* __restrict__ wh, __half* __restrict__ wl,
                                  int outch, int inch, int r)
{
    int o = blockIdx.x;
    int b = blockIdx.y;
    int i0 = threadIdx.x * 8;
    long outOff = ((long)b * gridDim.x + o) * inch + i0;
    if (o >= outch) {
        uint4 z = make_uint4(0u, 0u, 0u, 0u);
        *reinterpret_cast<uint4*>(wh + outOff) = z;
        *reinterpret_cast<uint4*>(wl + outOff) = z;
        return;
    }
    float vo[16];
    const float* vop = vout + ((long)b * outch + o) * r;
    #pragma unroll 4
    for (int rr = 0; rr < r; rr++) vo[rr] = vop[rr];

    const float* Wp  = W + (long)o * inch + i0;
    const float* vip = vin + ((long)b * inch + i0) * r;

    __align__(16) __half hb[8], lb[8];
    #pragma unroll
    for (int j = 0; j < 8; j++) {
        float v = Wp[j];
        const float* vi = vip + j * r;
        for (int rr = 0; rr < r; rr++) v += vo[rr] * vi[rr];
        __half hh = __float2half(v);
        hb[j] = hh;
        lb[j] = __float2half(v - __half2float(hh));
    }
    *reinterpret_cast<uint4*>(wh + outOff) = *reinterpret_cast<const uint4*>(hb);
    *reinterpret_cast<uint4*>(wl + outOff) = *reinterpret_cast<const uint4*>(lb);
}

__global__ void dconv_kernel(const float* __restrict__ x, const float* __restrict__ w,
                             const float* __restrict__ bias,
                             __half* __restrict__ yh, __half* __restrict__ yl)
{
    int idx = blockIdx.x * blockDim.x + threadIdx.x;
    if (idx >= BATCH * DIM * LEN) return;
    int t = idx & (LEN - 1);
    int c = (idx >> 11) & (DIM - 1);
    float acc = bias[c];
    #pragma unroll
    for (int k = 0; k < KS; k++)
        if (t - k >= 0) acc += w[c * KS + k] * x[idx - k];
    __half hh = __float2half(acc);
    yh[idx] = hh;
    yl[idx] = __float2half(acc - __half2float(hh));
}

// cos basis: Fc[n][k] = cos(2*pi*n*k/1024) for n<=512 && k<=512, else 0
__global__ void fill_Fc_kernel()
{
    int idx = blockIdx.x * blockDim.x + threadIdx.x;
    if (idx >= MC * KC) return;
    int n = idx / KC, k = idx - n * KC;
    float v = 0.f;
    if (n <= 512 && k <= 512) {
        int m = (n * k) & 1023;
        v = cospif((float)m * (1.0f / 512.0f));
    }
    __half hh = __float2half(v);
    g_Fch[idx] = hh;
    g_Fcl[idx] = __float2half(v - __half2float(hh));
}

// sin basis: Fs[n][k] = sin(2*pi*n*k/1024), n,k in [0,512)
__global__ void fill_Fs_kernel()
{
    int idx = blockIdx.x * blockDim.x + threadIdx.x;
    if (idx >= MS * KSR) return;
    int n = idx >> 9, k = idx & (KSR - 1);
    int m = (n * k) & 1023;
    float v = sinpif((float)m * (1.0f / 512.0f));
    __half hh = __float2half(v);
    g_Fsh[idx] = hh;
    g_Fsl[idx] = __float2half(v - __half2float(hh));
}

// pack spectrum into cos coeffs (rows 0..512 of sriC, pad 513..543 = 0)
// and sin coeffs (rows 1..511 of sriS, row 0 = 0)
__global__ void prep_sri_kernel()
{
    long idx = (long)blockIdx.x * blockDim.x + threadIdx.x;
    if (idx >= (long)BATCH * KC * LEN) return;
    int t = (int)(idx & (LEN - 1));
    int k = (int)((idx >> 11) % KC);
    int b = (int)(idx / ((long)KC * LEN));
    long cOff = ((long)b * KC + k) * LEN + t;
    if (k > 512) {
        g_sriCh[cOff] = __float2half(0.f);
        g_sriCl[cOff] = __float2half(0.f);
        return;
    }
    const float* hb = g_h3 + (long)b * MOPAD * LEN;
    float m = hb[(long)k * LEN + t];
    float p = hb[(long)(513 + k) * LEN + t];
    float mag = fminf(expf(m), 100.0f);
    float s, c;
    sincosf(p, &s, &c);
    const float invN = 1.0f / 1024.0f;
    float ck = (k == 0 || k == 512) ? invN : 2.0f * invN;
    float v0 = ck * mag * c;
    __half h0 = __float2half(v0);
    g_sriCh[cOff] = h0;
    g_sriCl[cOff] = __float2half(v0 - __half2float(h0));
    if (k < 512) {
        long sOff = ((long)b * KSR + k) * LEN + t;
        float v1 = (k == 0) ? 0.f : -2.0f * invN * mag * s;
        __half h1 = __float2half(v1);
        g_sriSh[sOff] = h1;
        g_sriSl[sOff] = __float2half(v1 - __half2float(h1));
    }
}

// frames row: [C(640) | S(512)]; fold: frames[n] = C[m] +/- S[m], m = min(n,1024-n)
__global__ void ola_kernel(const float* __restrict__ frames, float* __restrict__ out)
{
    int idx = blockIdx.x * blockDim.x + threadIdx.x;
    if (idx >= BATCH * OUTLEN) return;
    int b = idx >> 19;
    int pos = idx & (OUTLEN - 1);
    int tpad = pos + PADP;
    int fmax = tpad >> 8; if (fmax > LEN - 1) fmax = LEN - 1;
    int fmin = (tpad - (WIN - 1) + (HOP - 1)) >> 8; if (fmin < 0) fmin = 0;
    const float* fb = frames + (long)b * LEN * FRN;
    float num = 0.f, den = 0.f;
    for (int f = fmin; f <= fmax; f++) {
        int n = tpad - (f << 8);
        float w = 0.5f - 0.5f * cospif((float)n * (1.0f / 512.0f));
        int m = (n <= 512) ? n : 1024 - n;
        const float* row = fb + (long)f * FRN;
        float cv = row[m];
        float sv = (m < 512) ? row[640 + m] : 0.f;
        float v = (n <= 512) ? (cv + sv) : (cv - sv);
        num += v * w;
        den += w * w;
    }
    out[idx] = num / den;
}

// ---------------- launch ----------------
extern "C" void kernel_launch(void* const* d_in, const int* in_sizes, int n_in,
                              void* d_out, int out_size)
{
    const float* x       = (const float*)d_in[0];
    const float* g_outv  = (const float*)d_in[1];
    const float* dconv_w = (const float*)d_in[2];
    const float* dconv_b = (const float*)d_in[3];
    const float* p1_w    = (const float*)d_in[4];
    const float* p1_b    = (const float*)d_in[5];
    const float* p1_ain  = (const float*)d_in[6];
    const float* p1_aout = (const float*)d_in[7];
    const float* p2_w    = (const float*)d_in[8];
    const float* p2_b    = (const float*)d_in[9];
    const float* p2_ain  = (const float*)d_in[10];
    const float* p2_aout = (const float*)d_in[11];
    const float* out_w   = (const float*)d_in[12];
    const float* out_b   = (const float*)d_in[13];
    const float* out_ain = (const float*)d_in[14];
    const float* out_aout= (const float*)d_in[15];
    float* out = (float*)d_out;

    __half *h0h, *h0l, *h1h, *h1l, *h2h, *h2l;
    __half *sriCh, *sriCl, *sriSh, *sriSl;
    __half *w1h, *w1l, *w2h, *w2l, *woh, *wol, *Fch, *Fcl, *Fsh, *Fsl;
    float *h3, *frames;
    float *vin1, *vout1, *vin2, *vout2, *vino, *vouto;
    cudaGetSymbolAddress((void**)&h0h, g_h0h);  cudaGetSymbolAddress((void**)&h0l, g_h0l);
    cudaGetSymbolAddress((void**)&h1h, g_h1h);  cudaGetSymbolAddress((void**)&h1l, g_h1l);
    cudaGetSymbolAddress((void**)&h2h, g_h2h);  cudaGetSymbolAddress((void**)&h2l, g_h2l);
    cudaGetSymbolAddress((void**)&sriCh, g_sriCh); cudaGetSymbolAddress((void**)&sriCl, g_sriCl);
    cudaGetSymbolAddress((void**)&sriSh, g_sriSh); cudaGetSymbolAddress((void**)&sriSl, g_sriSl);
    cudaGetSymbolAddress((void**)&w1h, g_w1h);  cudaGetSymbolAddress((void**)&w1l, g_w1l);
    cudaGetSymbolAddress((void**)&w2h, g_w2h);  cudaGetSymbolAddress((void**)&w2l, g_w2l);
    cudaGetSymbolAddress((void**)&woh, g_woh);  cudaGetSymbolAddress((void**)&wol, g_wol);
    cudaGetSymbolAddress((void**)&Fch, g_Fch);  cudaGetSymbolAddress((void**)&Fcl, g_Fcl);
    cudaGetSymbolAddress((void**)&Fsh, g_Fsh);  cudaGetSymbolAddress((void**)&Fsl, g_Fsl);
    cudaGetSymbolAddress((void**)&h3, g_h3);
    cudaGetSymbolAddress((void**)&frames, g_frames);
    cudaGetSymbolAddress((void**)&vin1, g_vin1);  cudaGetSymbolAddress((void**)&vout1, g_vout1);
    cudaGetSymbolAddress((void**)&vin2, g_vin2);  cudaGetSymbolAddress((void**)&vout2, g_vout2);
    cudaGetSymbolAddress((void**)&vino, g_vino);  cudaGetSymbolAddress((void**)&vouto, g_vouto);

    cudaFuncSetAttribute(hmma_gemm, cudaFuncAttributeMaxDynamicSharedMemorySize, SMEM_TOT);

    fill_Fc_kernel<<<(MC * KC + 255) / 256, 256>>>();
    fill_Fs_kernel<<<(MS * KSR) / 256, 256>>>();

    gemv_all_kernel<<<GV_BLOCKS, 256>>>(g_outv,
                                        p1_ain, vin1, p1_aout, vout1,
                                        p2_ain, vin2, p2_aout, vout2,
                                        out_ain, vino, out_aout, vouto);

    {
        dim3 g1(M1, BATCH);    // inch=DIM -> 64 threads
        build_weff_kernel<<<g1, DIM / 8>>>(p1_w, vin1, vout1, w1h, w1l, M1, DIM, 12);
        dim3 g2(DIM, BATCH);   // inch=M1 -> 192 threads
        build_weff_kernel<<<g2, M1 / 8>>>(p2_w, vin2, vout2, w2h, w2l, DIM, M1, 12);
        dim3 g3(MOPAD, BATCH); // inch=DIM -> 64 threads
        build_weff_kernel<<<g3, DIM / 8>>>(out_w, vino, vouto, woh, wol, OUT_DIM, DIM, 16);
    }

    dconv_kernel<<<(BATCH * DIM * LEN) / 256, 256>>>(x, dconv_w, dconv_b, h0h, h0l);

    // p1: h1 = gelu(W1 @ h0 + b1)   [M=1536, K=512]
    {
        dim3 grid(LEN / 128, M1 / 128, BATCH);
        hmma_gemm<<<grid, 256, SMEM_TOT>>>(w1h, w1l, h0h, h0l, p1_b, h1h, h1l,
                                           M1, DIM, M1, 0, 1);
    }
    // p2: h2 = gelu(W2 @ h1 + b2)   [M=512, K=1536]
    {
        dim3 grid(LEN / 128, DIM / 128, BATCH);
        hmma_gemm<<<grid, 256, SMEM_TOT>>>(w2h, w2l, h1h, h1l, p2_b, h2h, h2l,
                                           DIM, M1, DIM, 0, 1);
    }
    // out head: h3 = Wo @ h2 + bo   [M=1152(pad), K=512] -> fp32 [m][t]
    {
        dim3 grid(LEN / 128, MOPAD / 128, BATCH);
        hmma_gemm<<<grid, 256, SMEM_TOT>>>(woh, wol, h2h, h2l, out_b, h3, nullptr,
                                           MOPAD, DIM, OUT_DIM, 1, 1);
    }

    prep_sri_kernel<<<(unsigned)(((long)BATCH * KC * LEN + 255) / 256), 256>>>();

    // irfft cos part: frames[b][t][0..639] = (Fc @ sriC)^T
    {
        dim3 grid(LEN / 128, MC / 128, BATCH);
        hmma_gemm<<<grid, 256, SMEM_TOT>>>(Fch, Fcl, sriCh, sriCl, nullptr, frames, nullptr,
                                           MC, KC, FRN, 2, 0);
    }
    // irfft sin part: frames[b][t][640..1151] = (Fs @ sriS)^T
    {
        dim3 grid(LEN / 128, MS / 128, BATCH);
        hmma_gemm<<<grid, 256, SMEM_TOT>>>(Fsh, Fsl, sriSh, sriSl, nullptr, frames + 640, nullptr,
                                           MS, KSR, FRN, 2, 0);
    }

    ola_kernel<<<(BATCH * OUTLEN) / 256, 256>>>(frames, out);
}

// round 17
// speedup vs baseline: 1.4894x; 1.4894x over previous
#include <cuda_runtime.h>
#include <cuda_fp16.h>
#include <math.h>
#include <stdint.h>

// ---------------- Problem constants ----------------
#define BATCH   8
#define DIM     512
#define LEN     2048
#define GIN     256
#define NFFT    1024
#define HOP     256
#define WIN     1024
#define OUT_DIM 1026
#define PADP    384
#define KS      5
#define OUTLEN  524288
#define M1      1536
#define MOPAD   1152

// irfft symmetric split: C part M=640 (513 valid) x K=544 (513 valid); S part 512 x 512
#define MC      640
#define KC      544
#define MS      512
#define KSR     512
#define FRN     1152   // frames row: [C 0..639 | S 640..1151]

// ---------------- Device scratch (static, no allocation) ----------------
__device__ __align__(256) __half g_h0h [BATCH * DIM * LEN];
__device__ __align__(256) __half g_h0l [BATCH * DIM * LEN];
__device__ __align__(256) __half g_h1h [BATCH * M1 * LEN];
__device__ __align__(256) __half g_h1l [BATCH * M1 * LEN];
__device__ __align__(256) __half g_h2h [BATCH * DIM * LEN];
__device__ __align__(256) __half g_h2l [BATCH * DIM * LEN];
__device__ __align__(256) float  g_h3  [BATCH * MOPAD * LEN];
__device__ __align__(256) __half g_sriCh[BATCH * KC  * LEN];
__device__ __align__(256) __half g_sriCl[BATCH * KC  * LEN];
__device__ __align__(256) __half g_sriSh[BATCH * KSR * LEN];
__device__ __align__(256) __half g_sriSl[BATCH * KSR * LEN];
__device__ __align__(256) float  g_frames[BATCH * LEN * FRN];  // [b][t][C|S]
__device__ __align__(256) __half g_w1h[BATCH * M1 * DIM];
__device__ __align__(256) __half g_w1l[BATCH * M1 * DIM];
__device__ __align__(256) __half g_w2h[BATCH * DIM * M1];
__device__ __align__(256) __half g_w2l[BATCH * DIM * M1];
__device__ __align__(256) __half g_woh[BATCH * MOPAD * DIM];
__device__ __align__(256) __half g_wol[BATCH * MOPAD * DIM];
__device__ __align__(256) __half g_Fch[MC * KC];
__device__ __align__(256) __half g_Fcl[MC * KC];
__device__ __align__(256) __half g_Fsh[MS * KSR];
__device__ __align__(256) __half g_Fsl[MS * KSR];
__device__ float g_vin1 [BATCH * DIM * 12];
__device__ float g_vout1[BATCH * 12 * M1];
__device__ float g_vin2 [BATCH * M1 * 12];
__device__ float g_vout2[BATCH * 12 * DIM];
__device__ float g_vino [BATCH * DIM * 16];
__device__ float g_vouto[BATCH * 16 * OUT_DIM];

// ---------------- PTX helpers (base ISA only) ----------------
__device__ __forceinline__ uint32_t smem_u32(const void* p) {
    uint32_t a;
    asm("{ .reg .u64 t; cvta.to.shared.u64 t, %1; cvt.u32.u64 %0, t; }" : "=r"(a) : "l"(p));
    return a;
}

__device__ __forceinline__ void cp16(uint32_t dst, const void* src) {
    asm volatile("cp.async.cg.shared.global [%0], [%1], 16;" :: "r"(dst), "l"(src));
}
#define CP_COMMIT() asm volatile("cp.async.commit_group;" ::: "memory")
template<int N> __device__ __forceinline__ void cp_wait() {
    asm volatile("cp.async.wait_group %0;" :: "n"(N) : "memory");
}

__device__ __forceinline__ void ldsm_x4(uint32_t* r, uint32_t addr) {
    asm volatile("ldmatrix.sync.aligned.m8n8.x4.shared.b16 {%0,%1,%2,%3}, [%4];"
                 : "=r"(r[0]), "=r"(r[1]), "=r"(r[2]), "=r"(r[3]) : "r"(addr));
}
__device__ __forceinline__ void ldsm_x4t(uint32_t* r, uint32_t addr) {
    asm volatile("ldmatrix.sync.aligned.m8n8.x4.trans.shared.b16 {%0,%1,%2,%3}, [%4];"
                 : "=r"(r[0]), "=r"(r[1]), "=r"(r[2]), "=r"(r[3]) : "r"(addr));
}

__device__ __forceinline__ void mma16816(float* c, const uint32_t* a, const uint32_t* b) {
    asm volatile("mma.sync.aligned.m16n8k16.row.col.f32.f16.f16.f32 "
                 "{%0,%1,%2,%3}, {%4,%5,%6,%7}, {%8,%9}, {%0,%1,%2,%3};"
                 : "+f"(c[0]), "+f"(c[1]), "+f"(c[2]), "+f"(c[3])
                 : "r"(a[0]), "r"(a[1]), "r"(a[2]), "r"(a[3]), "r"(b[0]), "r"(b[1]));
}

__device__ __forceinline__ float gelu_f(float v) {
    return 0.5f * v * (1.0f + erff(v * 0.70710678118654752f));
}

// ---------------- HMMA GEMM (3-stage pipeline, single-barrier mainloop) ----------------
// C[b][m][n] = sum_k A[b?][m][k] * B[b][k][n], hi/lo split operands (hh+hl+lh).
// BM=128 (blockIdx.y), BN=128 (blockIdx.x over LEN/128), batch=blockIdx.z.
// mode 0: +bias, gelu, write half hi/lo.  mode 1: +bias, fp32 [m][n].
// mode 2: fp32 TRANSPOSED frames rows; Mvalid = frame row stride (FRN), no bias.
#define BK 32
#define ASTR 80
#define BSTR 272
#define OFF_AH 0
#define OFF_AL 10240
#define OFF_BH 20480
#define OFF_BL 29184
#define SSTR   37888
#define NSTAGE 3
#define SMEM_TOT (NSTAGE * SSTR)
#define STG_STRIDE 132

__global__ __launch_bounds__(256, 2)
void hmma_gemm(const __half* __restrict__ Ah, const __half* __restrict__ Al,
               const __half* __restrict__ Bh, const __half* __restrict__ Bl,
               const float* __restrict__ bias,
               void* __restrict__ Ch, void* __restrict__ Cl,
               int M, int K, int Mvalid, int mode, int aBatched)
{
    extern __shared__ char smem[];
    uint32_t sb = smem_u32(smem);
    int tid = threadIdx.x, lane = tid & 31, wid = tid >> 5;
    int wm = wid & 3, wn = wid >> 2;
    int bz = blockIdx.z;
    int M0 = blockIdx.y * 128, N0 = blockIdx.x * 128;
    const int N = LEN;

    const __half* Abh = Ah + (aBatched ? (long)bz * M * K : 0);
    const __half* Abl = Al + (aBatched ? (long)bz * M * K : 0);
    const __half* Bbh = Bh + (long)bz * (long)K * N;
    const __half* Bbl = Bl + (long)bz * (long)K * N;

    int a_row = tid >> 2, a_col = tid & 3;
    int b_row = tid >> 4, b_col = tid & 15;

    float acc[2][8][4];
    #pragma unroll
    for (int i = 0; i < 2; i++)
        #pragma unroll
        for (int j = 0; j < 8; j++)
            #pragma unroll
            for (int q = 0; q < 4; q++) acc[i][j][q] = 0.f;

    int nIter = K / BK;

    auto load_stage = [&](int kc, int s) {
        uint32_t base = sb + s * SSTR;
        long ga0 = (long)(M0 + a_row) * K + kc * BK + a_col * 8;
        long ga1 = (long)(M0 + a_row + 64) * K + kc * BK + a_col * 8;
        cp16(base + OFF_AH + a_row * ASTR + a_col * 16, Abh + ga0);
        cp16(base + OFF_AH + (a_row + 64) * ASTR + a_col * 16, Abh + ga1);
        cp16(base + OFF_AL + a_row * ASTR + a_col * 16, Abl + ga0);
        cp16(base + OFF_AL + (a_row + 64) * ASTR + a_col * 16, Abl + ga1);
        long gb0 = (long)(kc * BK + b_row) * N + N0 + b_col * 8;
        long gb1 = (long)(kc * BK + b_row + 16) * N + N0 + b_col * 8;
        cp16(base + OFF_BH + b_row * BSTR + b_col * 16, Bbh + gb0);
        cp16(base + OFF_BH + (b_row + 16) * BSTR + b_col * 16, Bbh + gb1);
        cp16(base + OFF_BL + b_row * BSTR + b_col * 16, Bbl + gb0);
        cp16(base + OFF_BL + (b_row + 16) * BSTR + b_col * 16, Bbl + gb1);
        CP_COMMIT();
    };

    load_stage(0, 0);
    load_stage(1, 1);
    int s_cur = 0, s_load = 2;
    for (int it = 0; it < nIter; it++) {
        cp_wait<1>();
        __syncthreads();
        if (it + 2 < nIter) {
            load_stage(it + 2, s_load);
        }
        uint32_t base = sb + s_cur * SSTR;
        s_cur = (s_cur + 1 == NSTAGE) ? 0 : s_cur + 1;
        s_load = (s_load + 1 == NSTAGE) ? 0 : s_load + 1;

        #pragma unroll
        for (int ks = 0; ks < 2; ks++) {
            uint32_t ah[2][4], al[2][4];
            #pragma unroll
            for (int mt = 0; mt < 2; mt++) {
                uint32_t addr = base + OFF_AH
                    + (uint32_t)(wm * 32 + mt * 16 + (lane & 15)) * ASTR
                    + (uint32_t)(ks * 32 + (lane >> 4) * 16);
                ldsm_x4(ah[mt], addr);
                ldsm_x4(al[mt], addr + (OFF_AL - OFF_AH));
            }
            #pragma unroll
            for (int half = 0; half < 2; half++) {
                uint32_t bh[4][2], bl[4][2];
                #pragma unroll
                for (int j = 0; j < 2; j++) {
                    uint32_t rh[4], rl[4];
                    uint32_t addr = base + OFF_BH
                        + (uint32_t)(ks * 16 + (lane & 15)) * BSTR
                        + (uint32_t)(wn * 128 + half * 64 + j * 32 + (lane >> 4) * 16);
                    ldsm_x4t(rh, addr);
                    ldsm_x4t(rl, addr + (OFF_BL - OFF_BH));
                    bh[j*2][0] = rh[0]; bh[j*2][1] = rh[1];
                    bh[j*2+1][0] = rh[2]; bh[j*2+1][1] = rh[3];
                    bl[j*2][0] = rl[0]; bl[j*2][1] = rl[1];
                    bl[j*2+1][0] = rl[2]; bl[j*2+1][1] = rl[3];
                }
                #pragma unroll
                for (int mt = 0; mt < 2; mt++)
                    #pragma unroll
                    for (int j = 0; j < 4; j++) {
                        int nt = half * 4 + j;
                        mma16816(acc[mt][nt], ah[mt], bh[j]);
                        mma16816(acc[mt][nt], ah[mt], bl[j]);
                        mma16816(acc[mt][nt], al[mt], bh[j]);
                    }
            }
        }
        // no trailing barrier: with 3 stages, slot (it+2)%3 written next iter was
        // last read in iter it-1, ordered by every warp's top-of-loop barrier.
    }

    // ---- epilogue ----
    if (mode == 2) {
        __syncthreads();   // smem reuse: all warps done with mainloop stages
        int frn = Mvalid;  // frames row stride
        float* stg = (float*)smem;
        #pragma unroll
        for (int mt = 0; mt < 2; mt++)
            #pragma unroll
            for (int h = 0; h < 2; h++) {
                int m_loc = wm * 32 + mt * 16 + h * 8 + (lane >> 2);
                #pragma unroll
                for (int nt = 0; nt < 8; nt++) {
                    int n_loc = wn * 64 + nt * 8 + (lane & 3) * 2;
                    stg[(long)n_loc * STG_STRIDE + m_loc] = acc[mt][nt][h * 2 + 0];
                    stg[(long)(n_loc + 1) * STG_STRIDE + m_loc] = acc[mt][nt][h * 2 + 1];
                }
            }
        __syncthreads();
        int tt = tid >> 1, hf = tid & 1;
        float* dst = (float*)Ch + ((long)bz * LEN + N0 + tt) * frn + M0 + hf * 64;
        const float* src = stg + (long)tt * STG_STRIDE + hf * 64;
        #pragma unroll
        for (int j = 0; j < 64; j += 4)
            *reinterpret_cast<float4*>(dst + j) = *reinterpret_cast<const float4*>(src + j);
        return;
    }

    int rbase = M0 + wm * 32 + (lane >> 2);
    int cbase = N0 + wn * 64 + (lane & 3) * 2;
    #pragma unroll
    for (int mt = 0; mt < 2; mt++) {
        #pragma unroll
        for (int h = 0; h < 2; h++) {
            int row = rbase + mt * 16 + h * 8;
            float bv = (row < Mvalid) ? bias[row] : 0.f;
            #pragma unroll
            for (int nt = 0; nt < 8; nt++) {
                float v0 = acc[mt][nt][h * 2 + 0] + bv;
                float v1 = acc[mt][nt][h * 2 + 1] + bv;
                long off = (long)bz * M * N + (long)row * N + cbase + nt * 8;
                if (mode == 0) {
                    float gq0 = gelu_f(v0), gq1 = gelu_f(v1);
                    __half h0 = __float2half(gq0), h1 = __float2half(gq1);
                    __half l0 = __float2half(gq0 - __half2float(h0));
                    __half l1 = __float2half(gq1 - __half2float(h1));
                    *reinterpret_cast<__half2*>((__half*)Ch + off) = __halves2half2(h0, h1);
                    *reinterpret_cast<__half2*>((__half*)Cl + off) = __halves2half2(l0, l1);
                } else {
                    *reinterpret_cast<float2*>((float*)Ch + off) = make_float2(v0, v1);
                }
            }
        }
    }
}

// ---------------- small kernels ----------------
// fused 6-way gemv. aout outputs are written TRANSPOSED to [b][outch][r].
#define GV_R0 6144
#define GV_R1 18432
#define GV_R2 18432
#define GV_R3 6144
#define GV_R4 8192
#define GV_R5 16416
#define GV_E0 (GV_R0 * BATCH)
#define GV_E1 (GV_E0 + GV_R1 * BATCH)
#define GV_E2 (GV_E1 + GV_R2 * BATCH)
#define GV_E3 (GV_E2 + GV_R3 * BATCH)
#define GV_E4 (GV_E3 + GV_R4 * BATCH)
#define GV_E5 (GV_E4 + GV_R5 * BATCH)
#define GV_BLOCKS (GV_E5 / 8)

__global__ void gemv_all_kernel(const float* __restrict__ gvec,
                                const float* __restrict__ m0, float* __restrict__ o0,
                                const float* __restrict__ m1, float* __restrict__ o1,
                                const float* __restrict__ m2, float* __restrict__ o2,
                                const float* __restrict__ m3, float* __restrict__ o3,
                                const float* __restrict__ m4, float* __restrict__ o4,
                                const float* __restrict__ m5, float* __restrict__ o5)
{
    int w    = (blockIdx.x * blockDim.x + threadIdx.x) >> 5;
    int lane = threadIdx.x & 31;
    const float* mat; float* out; int rows, local, outch;
    if      (w < GV_E0) { mat = m0; out = o0; rows = GV_R0; local = w;         outch = 0; }
    else if (w < GV_E1) { mat = m1; out = o1; rows = GV_R1; local = w - GV_E0; outch = M1; }
    else if (w < GV_E2) { mat = m2; out = o2; rows = GV_R2; local = w - GV_E1; outch = 0; }
    else if (w < GV_E3) { mat = m3; out = o3; rows = GV_R3; local = w - GV_E2; outch = DIM; }
    else if (w < GV_E4) { mat = m4; out = o4; rows = GV_R4; local = w - GV_E3; outch = 0; }
    else if (w < GV_E5) { mat = m5; out = o5; rows = GV_R5; local = w - GV_E4; outch = OUT_DIM; }
    else return;
    int b = local / rows, o = local - b * rows;
    const float* r = mat + (long)o * GIN;
    const float* g = gvec + (long)b * GIN;
    float s = 0.f;
    #pragma unroll
    for (int i = 0; i < GIN / 32; i++) s += r[lane + 32 * i] * g[lane + 32 * i];
    #pragma unroll
    for (int off = 16; off; off >>= 1) s += __shfl_xor_sync(0xffffffffu, s, off);
    if (lane == 0) {
        int dst = o;
        if (outch) {
            int rr = o / outch, oc = o - rr * outch;
            int rfac = rows / outch;
            dst = oc * rfac + rr;
        }
        out[(long)b * rows + dst] = s;
    }
}

// scalar weff build (R14 form): one thread per output element, 256-thread blocks.
// vout in [b][outch][r] transposed layout: both factor reads contiguous.
__global__ void build_weff_kernel(const float* __restrict__ W, const float* __restrict__ vin,
                                  const float* __restrict__ vout,
                                  __half* __restrict__ wh, __half* __restrict__ wl,
                                  int outch, int inch, int r, int Mpad)
{
    long idx = (long)blockIdx.x * blockDim.x + threadIdx.x;
    long per = (long)Mpad * inch;
    if (idx >= per * BATCH) return;
    int b = (int)(idx / per);
    long rem = idx - (long)b * per;
    int o = (int)(rem / inch);
    int i = (int)(rem - (long)o * inch);
    float v = 0.f;
    if (o < outch) {
        v = W[(long)o * inch + i];
        const float* vi = vin + ((long)b * inch + i) * r;
        const float* vo = vout + ((long)b * outch + o) * r;
        for (int rr = 0; rr < r; rr++) v += vo[rr] * vi[rr];
    }
    __half hh = __float2half(v);
    wh[idx] = hh;
    wl[idx] = __float2half(v - __half2float(hh));
}

__global__ void dconv_kernel(const float* __restrict__ x, const float* __restrict__ w,
                             const float* __restrict__ bias,
                             __half* __restrict__ yh, __half* __restrict__ yl)
{
    int idx = blockIdx.x * blockDim.x + threadIdx.x;
    if (idx >= BATCH * DIM * LEN) return;
    int t = idx & (LEN - 1);
    int c = (idx >> 11) & (DIM - 1);
    float acc = bias[c];
    #pragma unroll
    for (int k = 0; k < KS; k++)
        if (t - k >= 0) acc += w[c * KS + k] * x[idx - k];
    __half hh = __float2half(acc);
    yh[idx] = hh;
    yl[idx] = __float2half(acc - __half2float(hh));
}

// cos basis: Fc[n][k] = cos(2*pi*n*k/1024) for n<=512 && k<=512, else 0
__global__ void fill_Fc_kernel()
{
    int idx = blockIdx.x * blockDim.x + threadIdx.x;
    if (idx >= MC * KC) return;
    int n = idx / KC, k = idx - n * KC;
    float v = 0.f;
    if (n <= 512 && k <= 512) {
        int m = (n * k) & 1023;
        v = cospif((float)m * (1.0f / 512.0f));
    }
    __half hh = __float2half(v);
    g_Fch[idx] = hh;
    g_Fcl[idx] = __float2half(v - __half2float(hh));
}

// sin basis: Fs[n][k] = sin(2*pi*n*k/1024), n,k in [0,512)
__global__ void fill_Fs_kernel()
{
    int idx = blockIdx.x * blockDim.x + threadIdx.x;
    if (idx >= MS * KSR) return;
    int n = idx >> 9, k = idx & (KSR - 1);
    int m = (n * k) & 1023;
    float v = sinpif((float)m * (1.0f / 512.0f));
    __half hh = __float2half(v);
    g_Fsh[idx] = hh;
    g_Fsl[idx] = __float2half(v - __half2float(hh));
}

// pack spectrum into cos coeffs (rows 0..512 of sriC, pad 513..543 = 0)
// and sin coeffs (rows 1..511 of sriS, row 0 = 0)
__global__ void prep_sri_kernel()
{
    long idx = (long)blockIdx.x * blockDim.x + threadIdx.x;
    if (idx >= (long)BATCH * KC * LEN) return;
    int t = (int)(idx & (LEN - 1));
    int k = (int)((idx >> 11) % KC);
    int b = (int)(idx / ((long)KC * LEN));
    long cOff = ((long)b * KC + k) * LEN + t;
    if (k > 512) {
        g_sriCh[cOff] = __float2half(0.f);
        g_sriCl[cOff] = __float2half(0.f);
        return;
    }
    const float* hb = g_h3 + (long)b * MOPAD * LEN;
    float m = hb[(long)k * LEN + t];
    float p = hb[(long)(513 + k) * LEN + t];
    float mag = fminf(expf(m), 100.0f);
    float s, c;
    sincosf(p, &s, &c);
    const float invN = 1.0f / 1024.0f;
    float ck = (k == 0 || k == 512) ? invN : 2.0f * invN;
    float v0 = ck * mag * c;
    __half h0 = __float2half(v0);
    g_sriCh[cOff] = h0;
    g_sriCl[cOff] = __float2half(v0 - __half2float(h0));
    if (k < 512) {
        long sOff = ((long)b * KSR + k) * LEN + t;
        float v1 = (k == 0) ? 0.f : -2.0f * invN * mag * s;
        __half h1 = __float2half(v1);
        g_sriSh[sOff] = h1;
        g_sriSl[sOff] = __float2half(v1 - __half2float(h1));
    }
}

// frames row: [C(640) | S(512)]; fold: frames[n] = C[m] +/- S[m], m = min(n,1024-n)
__global__ void ola_kernel(const float* __restrict__ frames, float* __restrict__ out)
{
    int idx = blockIdx.x * blockDim.x + threadIdx.x;
    if (idx >= BATCH * OUTLEN) return;
    int b = idx >> 19;
    int pos = idx & (OUTLEN - 1);
    int tpad = pos + PADP;
    int fmax = tpad >> 8; if (fmax > LEN - 1) fmax = LEN - 1;
    int fmin = (tpad - (WIN - 1) + (HOP - 1)) >> 8; if (fmin < 0) fmin = 0;
    const float* fb = frames + (long)b * LEN * FRN;
    float num = 0.f, den = 0.f;
    for (int f = fmin; f <= fmax; f++) {
        int n = tpad - (f << 8);
        float w = 0.5f - 0.5f * cospif((float)n * (1.0f / 512.0f));
        int m = (n <= 512) ? n : 1024 - n;
        const float* row = fb + (long)f * FRN;
        float cv = row[m];
        float sv = (m < 512) ? row[640 + m] : 0.f;
        float v = (n <= 512) ? (cv + sv) : (cv - sv);
        num += v * w;
        den += w * w;
    }
    out[idx] = num / den;
}

// ---------------- launch ----------------
extern "C" void kernel_launch(void* const* d_in, const int* in_sizes, int n_in,
                              void* d_out, int out_size)
{
    const float* x       = (const float*)d_in[0];
    const float* g_outv  = (const float*)d_in[1];
    const float* dconv_w = (const float*)d_in[2];
    const float* dconv_b = (const float*)d_in[3];
    const float* p1_w    = (const float*)d_in[4];
    const float* p1_b    = (const float*)d_in[5];
    const float* p1_ain  = (const float*)d_in[6];
    const float* p1_aout = (const float*)d_in[7];
    const float* p2_w    = (const float*)d_in[8];
    const float* p2_b    = (const float*)d_in[9];
    const float* p2_ain  = (const float*)d_in[10];
    const float* p2_aout = (const float*)d_in[11];
    const float* out_w   = (const float*)d_in[12];
    const float* out_b   = (const float*)d_in[13];
    const float* out_ain = (const float*)d_in[14];
    const float* out_aout= (const float*)d_in[15];
    float* out = (float*)d_out;

    __half *h0h, *h0l, *h1h, *h1l, *h2h, *h2l;
    __half *sriCh, *sriCl, *sriSh, *sriSl;
    __half *w1h, *w1l, *w2h, *w2l, *woh, *wol, *Fch, *Fcl, *Fsh, *Fsl;
    float *h3, *frames;
    float *vin1, *vout1, *vin2, *vout2, *vino, *vouto;
    cudaGetSymbolAddress((void**)&h0h, g_h0h);  cudaGetSymbolAddress((void**)&h0l, g_h0l);
    cudaGetSymbolAddress((void**)&h1h, g_h1h);  cudaGetSymbolAddress((void**)&h1l, g_h1l);
    cudaGetSymbolAddress((void**)&h2h, g_h2h);  cudaGetSymbolAddress((void**)&h2l, g_h2l);
    cudaGetSymbolAddress((void**)&sriCh, g_sriCh); cudaGetSymbolAddress((void**)&sriCl, g_sriCl);
    cudaGetSymbolAddress((void**)&sriSh, g_sriSh); cudaGetSymbolAddress((void**)&sriSl, g_sriSl);
    cudaGetSymbolAddress((void**)&w1h, g_w1h);  cudaGetSymbolAddress((void**)&w1l, g_w1l);
    cudaGetSymbolAddress((void**)&w2h, g_w2h);  cudaGetSymbolAddress((void**)&w2l, g_w2l);
    cudaGetSymbolAddress((void**)&woh, g_woh);  cudaGetSymbolAddress((void**)&wol, g_wol);
    cudaGetSymbolAddress((void**)&Fch, g_Fch);  cudaGetSymbolAddress((void**)&Fcl, g_Fcl);
    cudaGetSymbolAddress((void**)&Fsh, g_Fsh);  cudaGetSymbolAddress((void**)&Fsl, g_Fsl);
    cudaGetSymbolAddress((void**)&h3, g_h3);
    cudaGetSymbolAddress((void**)&frames, g_frames);
    cudaGetSymbolAddress((void**)&vin1, g_vin1);  cudaGetSymbolAddress((void**)&vout1, g_vout1);
    cudaGetSymbolAddress((void**)&vin2, g_vin2);  cudaGetSymbolAddress((void**)&vout2, g_vout2);
    cudaGetSymbolAddress((void**)&vino, g_vino);  cudaGetSymbolAddress((void**)&vouto, g_vouto);

    cudaFuncSetAttribute(hmma_gemm, cudaFuncAttributeMaxDynamicSharedMemorySize, SMEM_TOT);

    fill_Fc_kernel<<<(MC * KC + 255) / 256, 256>>>();
    fill_Fs_kernel<<<(MS * KSR) / 256, 256>>>();

    gemv_all_kernel<<<GV_BLOCKS, 256>>>(g_outv,
                                        p1_ain, vin1, p1_aout, vout1,
                                        p2_ain, vin2, p2_aout, vout2,
                                        out_ain, vino, out_aout, vouto);

    {
        long t1 = (long)BATCH * M1 * DIM;
        build_weff_kernel<<<(unsigned)((t1 + 255) / 256), 256>>>(p1_w, vin1, vout1, w1h, w1l, M1, DIM, 12, M1);
        long t2 = (long)BATCH * DIM * M1;
        build_weff_kernel<<<(unsigned)((t2 + 255) / 256), 256>>>(p2_w, vin2, vout2, w2h, w2l, DIM, M1, 12, DIM);
        long t3 = (long)BATCH * MOPAD * DIM;
        build_weff_kernel<<<(unsigned)((t3 + 255) / 256), 256>>>(out_w, vino, vouto, woh, wol, OUT_DIM, DIM, 16, MOPAD);
    }

    dconv_kernel<<<(BATCH * DIM * LEN) / 256, 256>>>(x, dconv_w, dconv_b, h0h, h0l);

    // p1: h1 = gelu(W1 @ h0 + b1)   [M=1536, K=512]
    {
        dim3 grid(LEN / 128, M1 / 128, BATCH);
        hmma_gemm<<<grid, 256, SMEM_TOT>>>(w1h, w1l, h0h, h0l, p1_b, h1h, h1l,
                                           M1, DIM, M1, 0, 1);
    }
    // p2: h2 = gelu(W2 @ h1 + b2)   [M=512, K=1536]
    {
        dim3 grid(LEN / 128, DIM / 128, BATCH);
        hmma_gemm<<<grid, 256, SMEM_TOT>>>(w2h, w2l, h1h, h1l, p2_b, h2h, h2l,
                                           DIM, M1, DIM, 0, 1);
    }
    // out head: h3 = Wo @ h2 + bo   [M=1152(pad), K=512] -> fp32 [m][t]
    {
        dim3 grid(LEN / 128, MOPAD / 128, BATCH);
        hmma_gemm<<<grid, 256, SMEM_TOT>>>(woh, wol, h2h, h2l, out_b, h3, nullptr,
                                           MOPAD, DIM, OUT_DIM, 1, 1);
    }

    prep_sri_kernel<<<(unsigned)(((long)BATCH * KC * LEN + 255) / 256), 256>>>();

    // irfft cos part: frames[b][t][0..639] = (Fc @ sriC)^T
    {
        dim3 grid(LEN / 128, MC / 128, BATCH);
        hmma_gemm<<<grid, 256, SMEM_TOT>>>(Fch, Fcl, sriCh, sriCl, nullptr, frames, nullptr,
                                           MC, KC, FRN, 2, 0);
    }
    // irfft sin part: frames[b][t][640..1151] = (Fs @ sriS)^T
    {
        dim3 grid(LEN / 128, MS / 128, BATCH);
        hmma_gemm<<<grid, 256, SMEM_TOT>>>(Fsh, Fsl, sriSh, sriSl, nullptr, frames + 640, nullptr,
                                           MS, KSR, FRN, 2, 0);
    }

    ola_kernel<<<(BATCH * OUTLEN) / 256, 256>>>(frames, out);
}